// round 8
// baseline (speedup 1.0000x reference)
#include <cuda_runtime.h>
#include <math.h>

// YoloLoss, fixed shape: input [32,255,76,76] f32, targets [32,20,5] f32, l int32.
// R8: division-free anchor argmax (cross-multiplied ratio compare), per-warp target
// pruning via xor-shuffle bounds + ballot (no smem round-trip, one barrier removed).
// Keeps R7: warp-cooperative class BCE, early input loads, atomicMax scatter map.

#define IN_H 76
#define IN_W 76
#define HW   (IN_H * IN_W)        // 5776
#define NT   20
#define NCLS 80
#define MAXB 2048

// per-block partials: 0=n_obj, 1=loc_sum, 2=cls_sum, 3=conf_num, 4=conf_mask_sum
__device__ double g_part[MAXB][5];
__device__ unsigned g_count = 0;

__constant__ float c_anchors[18] = {12,16, 19,36, 40,28, 36,75, 76,55,
                                    72,146, 142,110, 192,243, 459,401};

__device__ __forceinline__ float warp_sum(float v) {
    #pragma unroll
    for (int o = 16; o; o >>= 1) v += __shfl_down_sync(0xffffffffu, v, o);
    return v;
}
__device__ __forceinline__ float bfly_min(float v) {
    #pragma unroll
    for (int o = 16; o; o >>= 1) v = fminf(v, __shfl_xor_sync(0xffffffffu, v, o));
    return v;
}
__device__ __forceinline__ float bfly_max(float v) {
    #pragma unroll
    for (int o = 16; o; o >>= 1) v = fmaxf(v, __shfl_xor_sync(0xffffffffu, v, o));
    return v;
}
__device__ __forceinline__ double warp_sumd(double v) {
    #pragma unroll
    for (int o = 16; o; o >>= 1) v += __shfl_down_sync(0xffffffffu, v, o);
    return v;
}
__device__ __forceinline__ float ftanh(float x) {
    float r;
    asm("tanh.approx.f32 %0, %1;" : "=f"(r) : "f"(x));
    return r;
}
__device__ __forceinline__ float fsig(float x) {      // 1 MUFU sigmoid
    return fmaf(0.5f, ftanh(0.5f * x), 0.5f);
}
// softplus(z) = -log(sigmoid(-z)); equals clipped-BCE term exactly for |z| < ~16
__device__ __forceinline__ float fsoftplus(float z) {
    return __logf(1.0f + __expf(z));
}

__global__ void __launch_bounds__(128, 8)
yolo_fused(const float* __restrict__ inp, const float* __restrict__ tgt,
           const int* __restrict__ lptr, float* __restrict__ out)
{
    __shared__ float4   s_mm[NT];        // minx, maxx, miny, maxy
    __shared__ float    s_area[NT];
    __shared__ float    s_cx[NT], s_cy[NT], s_w[NT], s_h[NT];
    __shared__ int      s_cls[NT];
    __shared__ int      s_map[512];      // cell->target (-1 = none), atomicMax build
    __shared__ double   s_acc[5];
    __shared__ int      s_islast;

    const int b    = blockIdx.y;
    const int tid  = threadIdx.x;
    const int lane = tid & 31;
    const int base = blockIdx.x * 512;

    const int m4  = base + tid * 4;              // first cell of quad
    const bool vld = (m4 < 3 * HW);
    const int k   = m4 / HW;                     // constant across quad
    const int rem = m4 - k * HW;
    const int j   = rem / IN_W;
    const int i0  = rem - j * IN_W;
    const size_t eoff = ((size_t)b * 255 + (size_t)k * 85) * HW + rem;

    // ---- issue input loads FIRST (overlap with target preprocessing) ----
    float4 xv, yv, wv, hv, cv;
    if (vld) {
        xv = *(const float4*)(inp + eoff + 0 * HW);
        yv = *(const float4*)(inp + eoff + 1 * HW);
        wv = *(const float4*)(inp + eoff + 2 * HW);
        hv = *(const float4*)(inp + eoff + 3 * HW);
        cv = *(const float4*)(inp + eoff + 4 * HW);
    }
    const int l  = __ldg(lptr);
    const int m0 = 6 - 3 * l;

    // map init (parallel)
    s_map[tid] = -1; s_map[tid + 128] = -1; s_map[tid + 256] = -1; s_map[tid + 384] = -1;
    if (tid < 5) s_acc[tid] = 0.0;

    // ---- target preprocessing (concurrent with in-flight input loads) ----
    if (tid < NT) {
        const float* tp = tgt + ((size_t)b * NT + tid) * 5;
        float gx = tp[0] * (float)IN_W;
        float gy = tp[1] * (float)IN_H;
        float gw = tp[2] * (float)IN_W;
        float gh = tp[3] * (float)IN_H;
        // argmax over 9 anchors, division-free: r_a > r_b <=> inter_a*uni_b > inter_b*uni_a
        float binter = 0.0f, buni = 1e-30f; int bn = 0;
        #pragma unroll
        for (int a = 0; a < 9; a++) {
            float aw = c_anchors[2*a] * 0.125f, ah = c_anchors[2*a+1] * 0.125f;
            float inter = fminf(gw, aw) * fminf(gh, ah);
            float uni   = gw * gh + aw * ah - inter;
            if (inter * buni > binter * uni) { binter = inter; buni = uni; bn = a; }
        }
        int kk = bn - m0;
        int gi = (int)floorf(gx); gi = min(max(gi, 0), IN_W - 1);
        int gj = (int)floorf(gy); gj = min(max(gj, 0), IN_H - 1);
        if (kk >= 0 && kk < 3) {
            int d = kk * HW + gj * IN_W + gi - base;
            if ((unsigned)d < 512u) atomicMax(&s_map[d], tid);  // larger t wins = ref order
        }
        s_mm[tid] = make_float4(gx - gw * 0.5f, gx + gw * 0.5f,
                                gy - gh * 0.5f, gy + gh * 0.5f);
        s_area[tid] = gw * gh;
        s_cx[tid] = gx; s_cy[tid] = gy; s_w[tid] = gw; s_h[tid] = gh;
        s_cls[tid] = (int)tp[4];
    }

    // ---- decode (independent of shared; anchors from constant) ----
    float pnx[4], pxx[4], pny[4], pxy[4], pa[4];
    float cr[4];
    if (vld) {
        const float aw = c_anchors[2 * (m0 + k)]     * 0.125f;
        const float ah = c_anchors[2 * (m0 + k) + 1] * 0.125f;
        const float xr[4] = {xv.x, xv.y, xv.z, xv.w};
        const float yr[4] = {yv.x, yv.y, yv.z, yv.w};
        const float wr[4] = {wv.x, wv.y, wv.z, wv.w};
        const float hr[4] = {hv.x, hv.y, hv.z, hv.w};
        cr[0] = cv.x; cr[1] = cv.y; cr[2] = cv.z; cr[3] = cv.w;
        #pragma unroll
        for (int c = 0; c < 4; c++) {
            float px = (float)(i0 + c) + fsig(xr[c]);
            float py = (float)j        + fsig(yr[c]);
            float pw = __expf(wr[c]) * aw;
            float ph = __expf(hr[c]) * ah;
            pnx[c] = px - pw * 0.5f;  pxx[c] = px + pw * 0.5f;
            pny[c] = py - ph * 0.5f;  pxy[c] = py + ph * 0.5f;
            pa[c]  = pw * ph;
        }
    }

    // ---- per-warp bounds via butterflies (no smem, no extra sync) ----
    float pamin = 1e30f, pamax = -1e30f, pnymin = 1e30f, pxymax = -1e30f;
    if (vld) {
        #pragma unroll
        for (int c = 0; c < 4; c++) {
            pamin  = fminf(pamin,  pa[c]);  pamax  = fmaxf(pamax,  pa[c]);
            pnymin = fminf(pnymin, pny[c]); pxymax = fmaxf(pxymax, pxy[c]);
        }
    }
    const float wpamin  = bfly_min(pamin);
    const float wpamax  = bfly_max(pamax);
    const float wpnymin = bfly_min(pnymin);
    const float wpxymax = bfly_max(pxymax);

    __syncthreads();   // targets + map ready

    // ---- per-warp prune: lanes 0..19 test their target against warp bounds ----
    unsigned keepmsk;
    {
        bool keep = false;
        if (lane < NT) {
            float ar = s_area[lane];
            float4 mm = s_mm[lane];
            // trigger 3*inter-ar > pa needs ar/2 < pa < 2*ar (margined) and y-overlap
            keep = (wpamin < 2.0002f * ar) && (2.0002f * wpamax > ar)
                && (mm.w >= wpnymin) && (mm.z <= wpxymax);
        }
        keepmsk = __ballot_sync(0xffffffffu, keep);
    }

    float objf = 0.f, loc = 0.f, clsl = 0.f, confn = 0.f, cmask = 0.f;
    bool objc[4] = {false, false, false, false};

    if (vld) {
        // ignore loop over surviving targets (warp-uniform mask walk)
        float ignmax[4] = {-1e30f, -1e30f, -1e30f, -1e30f};
        unsigned msk = keepmsk;
        while (msk) {
            const int t = __ffs(msk) - 1;
            msk &= msk - 1;
            const float4 mm = s_mm[t];
            const float  ar = s_area[t];
            #pragma unroll
            for (int c = 0; c < 4; c++) {
                float iw = fminf(mm.y, pxx[c]) - fmaxf(mm.x, pnx[c]);
                float ih = fminf(mm.w, pxy[c]) - fmaxf(mm.z, pny[c]);
                float inter = fmaxf(iw, 0.f) * fmaxf(ih, 0.f);
                ignmax[c] = fmaxf(ignmax[c], fmaf(3.0f, inter, -ar));
            }
        }

        const int4 mi = ((const int4*)s_map)[tid];
        const int tq[4] = {mi.x, mi.y, mi.z, mi.w};

        #pragma unroll
        for (int c = 0; c < 4; c++) {
            const int t = tq[c];
            const bool isobj = (t >= 0);
            objc[c] = isobj;
            objf += isobj ? 1.0f : 0.0f;

            float cm = (isobj || ignmax[c] <= pa[c]) ? 1.0f : 0.0f;
            confn += cm * fsoftplus(isobj ? -cr[c] : cr[c]);
            cmask += cm;

            if (isobj) {   // rare: CIoU (class BCE handled cooperatively below)
                float pw = pxx[c] - pnx[c];
                float ph = pxy[c] - pny[c];
                float px = 0.5f * (pnx[c] + pxx[c]);
                float py = 0.5f * (pny[c] + pxy[c]);
                float gx = s_cx[t], gy = s_cy[t], gw = s_w[t], gh = s_h[t];
                float g_minx = gx - gw*0.5f, g_maxx = gx + gw*0.5f;
                float g_miny = gy - gh*0.5f, g_maxy = gy + gh*0.5f;
                float iw = fmaxf(fminf(g_maxx, pxx[c]) - fmaxf(g_minx, pnx[c]), 0.f);
                float ih = fmaxf(fminf(g_maxy, pxy[c]) - fmaxf(g_miny, pny[c]), 0.f);
                float inter = iw * ih;
                float uni   = fmaxf(pa[c] + gw * gh - inter, 1e-6f);
                float iou   = inter / uni;
                float dx = px - gx, dy = py - gy;
                float cd = dx * dx + dy * dy;
                float ew = fmaxf(fmaxf(g_maxx, pxx[c]) - fminf(g_minx, pnx[c]), 0.f);
                float eh = fmaxf(fmaxf(g_maxy, pxy[c]) - fminf(g_miny, pny[c]), 0.f);
                float ed = fmaxf(ew * ew + eh * eh, 1e-6f);
                float da = atanf(pw / fmaxf(ph, 1e-6f))
                         - atanf(gw / fmaxf(gh, 1e-6f));
                float v  = 0.405284734569351f * da * da;  // 4/pi^2
                float alpha = v / fmaxf(1.0f - iou + v, 1e-6f);
                loc += 1.0f - (iou - cd / ed - alpha * v);
            }
        }
    }

    // ---- warp-cooperative class BCE over obj cells (32 lanes split 80 ch) ----
    #pragma unroll
    for (int c = 0; c < 4; c++) {
        unsigned msk = __ballot_sync(0xffffffffu, vld && objc[c]);
        while (msk) {
            const int src = __ffs(msk) - 1;
            msk &= msk - 1;
            const int cell = __shfl_sync(0xffffffffu, m4 + c, src);
            const int t    = s_map[cell - base];          // broadcast LDS
            const int cc   = s_cls[t];
            const int k2   = cell / HW;
            const int rem2 = cell - k2 * HW;
            const size_t off = ((size_t)b * 255 + (size_t)k2 * 85) * HW + rem2;
            float cs = 0.0f;
            #pragma unroll
            for (int q = 0; q < 3; q++) {
                int ch = lane + q * 32;
                if (ch < NCLS) {
                    float z = inp[off + (size_t)(5 + ch) * HW];
                    cs += fsoftplus((ch == cc) ? -z : z);
                }
            }
            cs = warp_sum(cs);
            if (lane == 0) clsl += cs;
        }
    }

    // block reduction
    float vals[5] = {objf, loc, clsl, confn, cmask};
    #pragma unroll
    for (int q = 0; q < 5; q++) {
        float v = warp_sum(vals[q]);
        if (lane == 0 && v != 0.0f) atomicAdd(&s_acc[q], (double)v);
    }
    __syncthreads();

    const int nblocks = gridDim.x * gridDim.y;
    const int bid = blockIdx.y * gridDim.x + blockIdx.x;
    if (tid < 5) g_part[bid][tid] = s_acc[tid];

    if (tid == 0) {
        __threadfence();
        unsigned v = atomicAdd(&g_count, 1u);
        s_islast = (v == (unsigned)(nblocks - 1));
        if (s_islast) g_count = 0;    // self-reset -> graph-replay deterministic
    }
    __syncthreads();
    if (!s_islast) return;

    double acc[5] = {0, 0, 0, 0, 0};
    for (int r = tid; r < nblocks; r += blockDim.x) {
        #pragma unroll
        for (int q = 0; q < 5; q++) acc[q] += g_part[r][q];
    }
    __shared__ double s_fin[5];
    if (tid < 5) s_fin[tid] = 0.0;
    __syncthreads();
    #pragma unroll
    for (int q = 0; q < 5; q++) {
        double v = warp_sumd(acc[q]);
        if (lane == 0 && v != 0.0) atomicAdd(&s_fin[q], v);
    }
    __syncthreads();
    if (tid == 0) {
        double n_obj = s_fin[0] < 1.0 ? 1.0 : s_fin[0];
        double cms   = s_fin[4] < 1.0 ? 1.0 : s_fin[4];
        const double balance = (l == 0) ? 0.4 : (l == 1 ? 1.0 : 4.0);
        const double obj_ratio = 5.0 * 608.0 * 608.0 / (416.0 * 416.0);
        double loss = s_fin[1] / n_obj * 0.05
                    + s_fin[3] / cms * balance * obj_ratio
                    + s_fin[2] / (n_obj * (double)NCLS);
        out[0] = (float)loss;
    }
}

extern "C" void kernel_launch(void* const* d_in, const int* in_sizes, int n_in,
                              void* d_out, int out_size)
{
    const float* inp  = (const float*)d_in[0];
    const float* tgt  = (const float*)d_in[1];
    const int*   lptr = (const int*)d_in[2];
    float* out = (float*)d_out;

    const int bs = in_sizes[0] / (255 * HW);        // 32
    const int blocks_x = (3 * HW / 4 + 127) / 128;  // 34

    yolo_fused<<<dim3(blocks_x, bs), 128>>>(inp, tgt, lptr, out);
}

// round 9
// speedup vs baseline: 1.1194x; 1.1194x over previous
#include <cuda_runtime.h>
#include <math.h>

// YoloLoss, fixed shape: input [32,255,76,76] f32, targets [32,20,5] f32, l int32.
// R9: 256-thread blocks (grid 544) — halves per-block epilogue/atomic/tail costs;
// safe now that the divergent class tail is warp-cooperative (R7). Keeps R8:
// division-free argmax, per-warp ballot pruning, early input loads, atomicMax map.

#define IN_H 76
#define IN_W 76
#define HW   (IN_H * IN_W)        // 5776
#define NT   20
#define NCLS 80
#define MAXB 1024

// per-block partials: 0=n_obj, 1=loc_sum, 2=cls_sum, 3=conf_num, 4=conf_mask_sum
__device__ double g_part[MAXB][5];
__device__ unsigned g_count = 0;

__constant__ float c_anchors[18] = {12,16, 19,36, 40,28, 36,75, 76,55,
                                    72,146, 142,110, 192,243, 459,401};

__device__ __forceinline__ float warp_sum(float v) {
    #pragma unroll
    for (int o = 16; o; o >>= 1) v += __shfl_down_sync(0xffffffffu, v, o);
    return v;
}
__device__ __forceinline__ float bfly_min(float v) {
    #pragma unroll
    for (int o = 16; o; o >>= 1) v = fminf(v, __shfl_xor_sync(0xffffffffu, v, o));
    return v;
}
__device__ __forceinline__ float bfly_max(float v) {
    #pragma unroll
    for (int o = 16; o; o >>= 1) v = fmaxf(v, __shfl_xor_sync(0xffffffffu, v, o));
    return v;
}
__device__ __forceinline__ double warp_sumd(double v) {
    #pragma unroll
    for (int o = 16; o; o >>= 1) v += __shfl_down_sync(0xffffffffu, v, o);
    return v;
}
__device__ __forceinline__ float ftanh(float x) {
    float r;
    asm("tanh.approx.f32 %0, %1;" : "=f"(r) : "f"(x));
    return r;
}
__device__ __forceinline__ float fsig(float x) {      // 1 MUFU sigmoid
    return fmaf(0.5f, ftanh(0.5f * x), 0.5f);
}
// softplus(z) = -log(sigmoid(-z)); equals clipped-BCE term exactly for |z| < ~16
__device__ __forceinline__ float fsoftplus(float z) {
    return __logf(1.0f + __expf(z));
}

__global__ void __launch_bounds__(256, 4)
yolo_fused(const float* __restrict__ inp, const float* __restrict__ tgt,
           const int* __restrict__ lptr, float* __restrict__ out)
{
    __shared__ float4   s_mm[NT];        // minx, maxx, miny, maxy
    __shared__ float    s_area[NT];
    __shared__ float    s_cx[NT], s_cy[NT], s_w[NT], s_h[NT];
    __shared__ int      s_cls[NT];
    __shared__ int      s_map[1024];     // cell->target (-1 = none), atomicMax build
    __shared__ double   s_acc[5];
    __shared__ int      s_islast;

    const int b    = blockIdx.y;
    const int tid  = threadIdx.x;
    const int lane = tid & 31;
    const int base = blockIdx.x * 1024;

    const int m4  = base + tid * 4;              // first cell of quad
    const bool vld = (m4 < 3 * HW);
    const int k   = m4 / HW;                     // constant across quad
    const int rem = m4 - k * HW;
    const int j   = rem / IN_W;
    const int i0  = rem - j * IN_W;
    const size_t eoff = ((size_t)b * 255 + (size_t)k * 85) * HW + rem;

    // ---- issue input loads FIRST (overlap with target preprocessing) ----
    float4 xv, yv, wv, hv, cv;
    if (vld) {
        xv = *(const float4*)(inp + eoff + 0 * HW);
        yv = *(const float4*)(inp + eoff + 1 * HW);
        wv = *(const float4*)(inp + eoff + 2 * HW);
        hv = *(const float4*)(inp + eoff + 3 * HW);
        cv = *(const float4*)(inp + eoff + 4 * HW);
    }
    const int l  = __ldg(lptr);
    const int m0 = 6 - 3 * l;

    // map init (parallel)
    s_map[tid] = -1; s_map[tid + 256] = -1; s_map[tid + 512] = -1; s_map[tid + 768] = -1;
    if (tid < 5) s_acc[tid] = 0.0;

    // ---- target preprocessing (concurrent with in-flight input loads) ----
    if (tid < NT) {
        const float* tp = tgt + ((size_t)b * NT + tid) * 5;
        float gx = tp[0] * (float)IN_W;
        float gy = tp[1] * (float)IN_H;
        float gw = tp[2] * (float)IN_W;
        float gh = tp[3] * (float)IN_H;
        // argmax over 9 anchors, division-free: r_a > r_b <=> inter_a*uni_b > inter_b*uni_a
        float binter = 0.0f, buni = 1e-30f; int bn = 0;
        #pragma unroll
        for (int a = 0; a < 9; a++) {
            float aw = c_anchors[2*a] * 0.125f, ah = c_anchors[2*a+1] * 0.125f;
            float inter = fminf(gw, aw) * fminf(gh, ah);
            float uni   = gw * gh + aw * ah - inter;
            if (inter * buni > binter * uni) { binter = inter; buni = uni; bn = a; }
        }
        int kk = bn - m0;
        int gi = (int)floorf(gx); gi = min(max(gi, 0), IN_W - 1);
        int gj = (int)floorf(gy); gj = min(max(gj, 0), IN_H - 1);
        if (kk >= 0 && kk < 3) {
            int d = kk * HW + gj * IN_W + gi - base;
            if ((unsigned)d < 1024u) atomicMax(&s_map[d], tid);  // larger t wins = ref order
        }
        s_mm[tid] = make_float4(gx - gw * 0.5f, gx + gw * 0.5f,
                                gy - gh * 0.5f, gy + gh * 0.5f);
        s_area[tid] = gw * gh;
        s_cx[tid] = gx; s_cy[tid] = gy; s_w[tid] = gw; s_h[tid] = gh;
        s_cls[tid] = (int)tp[4];
    }

    // ---- decode (independent of shared; anchors from constant) ----
    float pnx[4], pxx[4], pny[4], pxy[4], pa[4];
    float cr[4];
    if (vld) {
        const float aw = c_anchors[2 * (m0 + k)]     * 0.125f;
        const float ah = c_anchors[2 * (m0 + k) + 1] * 0.125f;
        const float xr[4] = {xv.x, xv.y, xv.z, xv.w};
        const float yr[4] = {yv.x, yv.y, yv.z, yv.w};
        const float wr[4] = {wv.x, wv.y, wv.z, wv.w};
        const float hr[4] = {hv.x, hv.y, hv.z, hv.w};
        cr[0] = cv.x; cr[1] = cv.y; cr[2] = cv.z; cr[3] = cv.w;
        #pragma unroll
        for (int c = 0; c < 4; c++) {
            float px = (float)(i0 + c) + fsig(xr[c]);
            float py = (float)j        + fsig(yr[c]);
            float pw = __expf(wr[c]) * aw;
            float ph = __expf(hr[c]) * ah;
            pnx[c] = px - pw * 0.5f;  pxx[c] = px + pw * 0.5f;
            pny[c] = py - ph * 0.5f;  pxy[c] = py + ph * 0.5f;
            pa[c]  = pw * ph;
        }
    }

    // ---- per-warp bounds via butterflies (no smem, no extra sync) ----
    float pamin = 1e30f, pamax = -1e30f, pnymin = 1e30f, pxymax = -1e30f;
    if (vld) {
        #pragma unroll
        for (int c = 0; c < 4; c++) {
            pamin  = fminf(pamin,  pa[c]);  pamax  = fmaxf(pamax,  pa[c]);
            pnymin = fminf(pnymin, pny[c]); pxymax = fmaxf(pxymax, pxy[c]);
        }
    }
    const float wpamin  = bfly_min(pamin);
    const float wpamax  = bfly_max(pamax);
    const float wpnymin = bfly_min(pnymin);
    const float wpxymax = bfly_max(pxymax);

    __syncthreads();   // targets + map ready

    // ---- per-warp prune: lanes 0..19 test their target against warp bounds ----
    unsigned keepmsk;
    {
        bool keep = false;
        if (lane < NT) {
            float ar = s_area[lane];
            float4 mm = s_mm[lane];
            // trigger 3*inter-ar > pa needs ar/2 < pa < 2*ar (margined) and y-overlap
            keep = (wpamin < 2.0002f * ar) && (2.0002f * wpamax > ar)
                && (mm.w >= wpnymin) && (mm.z <= wpxymax);
        }
        keepmsk = __ballot_sync(0xffffffffu, keep);
    }

    float objf = 0.f, loc = 0.f, clsl = 0.f, confn = 0.f, cmask = 0.f;
    bool objc[4] = {false, false, false, false};

    if (vld) {
        // ignore loop over surviving targets (warp-uniform mask walk)
        float ignmax[4] = {-1e30f, -1e30f, -1e30f, -1e30f};
        unsigned msk = keepmsk;
        while (msk) {
            const int t = __ffs(msk) - 1;
            msk &= msk - 1;
            const float4 mm = s_mm[t];
            const float  ar = s_area[t];
            #pragma unroll
            for (int c = 0; c < 4; c++) {
                float iw = fminf(mm.y, pxx[c]) - fmaxf(mm.x, pnx[c]);
                float ih = fminf(mm.w, pxy[c]) - fmaxf(mm.z, pny[c]);
                float inter = fmaxf(iw, 0.f) * fmaxf(ih, 0.f);
                ignmax[c] = fmaxf(ignmax[c], fmaf(3.0f, inter, -ar));
            }
        }

        const int4 mi = ((const int4*)s_map)[tid];
        const int tq[4] = {mi.x, mi.y, mi.z, mi.w};

        #pragma unroll
        for (int c = 0; c < 4; c++) {
            const int t = tq[c];
            const bool isobj = (t >= 0);
            objc[c] = isobj;
            objf += isobj ? 1.0f : 0.0f;

            float cm = (isobj || ignmax[c] <= pa[c]) ? 1.0f : 0.0f;
            confn += cm * fsoftplus(isobj ? -cr[c] : cr[c]);
            cmask += cm;

            if (isobj) {   // rare: CIoU (class BCE handled cooperatively below)
                float pw = pxx[c] - pnx[c];
                float ph = pxy[c] - pny[c];
                float px = 0.5f * (pnx[c] + pxx[c]);
                float py = 0.5f * (pny[c] + pxy[c]);
                float gx = s_cx[t], gy = s_cy[t], gw = s_w[t], gh = s_h[t];
                float g_minx = gx - gw*0.5f, g_maxx = gx + gw*0.5f;
                float g_miny = gy - gh*0.5f, g_maxy = gy + gh*0.5f;
                float iw = fmaxf(fminf(g_maxx, pxx[c]) - fmaxf(g_minx, pnx[c]), 0.f);
                float ih = fmaxf(fminf(g_maxy, pxy[c]) - fmaxf(g_miny, pny[c]), 0.f);
                float inter = iw * ih;
                float uni   = fmaxf(pa[c] + gw * gh - inter, 1e-6f);
                float iou   = inter / uni;
                float dx = px - gx, dy = py - gy;
                float cd = dx * dx + dy * dy;
                float ew = fmaxf(fmaxf(g_maxx, pxx[c]) - fminf(g_minx, pnx[c]), 0.f);
                float eh = fmaxf(fmaxf(g_maxy, pxy[c]) - fminf(g_miny, pny[c]), 0.f);
                float ed = fmaxf(ew * ew + eh * eh, 1e-6f);
                float da = atanf(pw / fmaxf(ph, 1e-6f))
                         - atanf(gw / fmaxf(gh, 1e-6f));
                float v  = 0.405284734569351f * da * da;  // 4/pi^2
                float alpha = v / fmaxf(1.0f - iou + v, 1e-6f);
                loc += 1.0f - (iou - cd / ed - alpha * v);
            }
        }
    }

    // ---- warp-cooperative class BCE over obj cells (32 lanes split 80 ch) ----
    #pragma unroll
    for (int c = 0; c < 4; c++) {
        unsigned msk = __ballot_sync(0xffffffffu, vld && objc[c]);
        while (msk) {
            const int src = __ffs(msk) - 1;
            msk &= msk - 1;
            const int cell = __shfl_sync(0xffffffffu, m4 + c, src);
            const int t    = s_map[cell - base];          // broadcast LDS
            const int cc   = s_cls[t];
            const int k2   = cell / HW;
            const int rem2 = cell - k2 * HW;
            const size_t off = ((size_t)b * 255 + (size_t)k2 * 85) * HW + rem2;
            float cs = 0.0f;
            #pragma unroll
            for (int q = 0; q < 3; q++) {
                int ch = lane + q * 32;
                if (ch < NCLS) {
                    float z = inp[off + (size_t)(5 + ch) * HW];
                    cs += fsoftplus((ch == cc) ? -z : z);
                }
            }
            cs = warp_sum(cs);
            if (lane == 0) clsl += cs;
        }
    }

    // block reduction
    float vals[5] = {objf, loc, clsl, confn, cmask};
    #pragma unroll
    for (int q = 0; q < 5; q++) {
        float v = warp_sum(vals[q]);
        if (lane == 0 && v != 0.0f) atomicAdd(&s_acc[q], (double)v);
    }
    __syncthreads();

    const int nblocks = gridDim.x * gridDim.y;
    const int bid = blockIdx.y * gridDim.x + blockIdx.x;
    if (tid < 5) g_part[bid][tid] = s_acc[tid];

    if (tid == 0) {
        __threadfence();
        unsigned v = atomicAdd(&g_count, 1u);
        s_islast = (v == (unsigned)(nblocks - 1));
        if (s_islast) g_count = 0;    // self-reset -> graph-replay deterministic
    }
    __syncthreads();
    if (!s_islast) return;

    double acc[5] = {0, 0, 0, 0, 0};
    for (int r = tid; r < nblocks; r += blockDim.x) {
        #pragma unroll
        for (int q = 0; q < 5; q++) acc[q] += g_part[r][q];
    }
    __shared__ double s_fin[5];
    if (tid < 5) s_fin[tid] = 0.0;
    __syncthreads();
    #pragma unroll
    for (int q = 0; q < 5; q++) {
        double v = warp_sumd(acc[q]);
        if (lane == 0 && v != 0.0) atomicAdd(&s_fin[q], v);
    }
    __syncthreads();
    if (tid == 0) {
        double n_obj = s_fin[0] < 1.0 ? 1.0 : s_fin[0];
        double cms   = s_fin[4] < 1.0 ? 1.0 : s_fin[4];
        const double balance = (l == 0) ? 0.4 : (l == 1 ? 1.0 : 4.0);
        const double obj_ratio = 5.0 * 608.0 * 608.0 / (416.0 * 416.0);
        double loss = s_fin[1] / n_obj * 0.05
                    + s_fin[3] / cms * balance * obj_ratio
                    + s_fin[2] / (n_obj * (double)NCLS);
        out[0] = (float)loss;
    }
}

extern "C" void kernel_launch(void* const* d_in, const int* in_sizes, int n_in,
                              void* d_out, int out_size)
{
    const float* inp  = (const float*)d_in[0];
    const float* tgt  = (const float*)d_in[1];
    const int*   lptr = (const int*)d_in[2];
    float* out = (float*)d_out;

    const int bs = in_sizes[0] / (255 * HW);        // 32
    const int blocks_x = (3 * HW / 4 + 255) / 256;  // 17

    yolo_fused<<<dim3(blocks_x, bs), 256>>>(inp, tgt, lptr, out);
}